// round 12
// baseline (speedup 1.0000x reference)
#include <cuda_runtime.h>
#include <math.h>
#include <float.h>

// Shapes (fixed): x [8,512,64,64] f32; w1 [32,512]; b1 [32]; w2 [512,32]; b2 [512]
#define NPLANES 4096
#define PLANE_ELEMS 4096
#define HW 64
#define NEG_INF (-FLT_MAX)

// Per-CTA smem: rowS/rowB for 44 srows (32 output rows + halo/pad), stride 64.
#define RSTR 64
#define NSROW 44

// Scratch (no allocations allowed -> device globals)
__device__ float g_gap[NPLANES];
__device__ int   g_q[NPLANES];
__device__ float g_fb[NPLANES];

// ---------------------------------------------------------------------------
// Kernel 1: per-plane mean
// ---------------------------------------------------------------------------
__global__ __launch_bounds__(256) void gap_kernel(const float* __restrict__ x) {
    const int plane = blockIdx.x;
    const float4* __restrict__ p =
        reinterpret_cast<const float4*>(x + (size_t)plane * PLANE_ELEMS);

    float sum = 0.f;
    #pragma unroll 4
    for (int i = threadIdx.x; i < PLANE_ELEMS / 4; i += 256) {
        float4 v = p[i];
        sum += (v.x + v.y) + (v.z + v.w);
    }
    #pragma unroll
    for (int off = 16; off > 0; off >>= 1)
        sum += __shfl_down_sync(0xffffffffu, sum, off);

    __shared__ float warp_sums[8];
    const int lane = threadIdx.x & 31, wid = threadIdx.x >> 5;
    if (lane == 0) warp_sums[wid] = sum;
    __syncthreads();
    if (threadIdx.x == 0) {
        float t = 0.f;
        #pragma unroll
        for (int i = 0; i < 8; i++) t += warp_sums[i];
        g_gap[plane] = t * (1.0f / (float)PLANE_ELEMS);
    }
}

// ---------------------------------------------------------------------------
// Kernel 2: SE bottleneck + routing
// ---------------------------------------------------------------------------
__global__ __launch_bounds__(512) void se_kernel(const float* __restrict__ w1,
                                                 const float* __restrict__ b1,
                                                 const float* __restrict__ w2,
                                                 const float* __restrict__ b2) {
    __shared__ float sgap[512];
    __shared__ float shmid[32];
    const int b = blockIdx.x;
    const int t = threadIdx.x;

    sgap[t] = g_gap[b * 512 + t];
    __syncthreads();

    if (t < 32) {
        float acc = b1[t];
        const float* wr = w1 + t * 512;
        #pragma unroll 8
        for (int k = 0; k < 512; k++) acc = fmaf(sgap[k], wr[k], acc);
        shmid[t] = fmaxf(acc, 0.f);
    }
    __syncthreads();

    float acc = b2[t];
    const float* wr = w2 + t * 32;
    #pragma unroll
    for (int j = 0; j < 32; j++) acc = fmaf(shmid[j], wr[j], acc);
    const float s = fmaxf(acc, 0.f);

    int q = (int)floorf(s);
    q = min(max(q, 0), 5);
    const int plane = b * 512 + t;
    g_q[plane]  = q;
    g_fb[plane] = s - (float)q;
}

// ---------------------------------------------------------------------------
__device__ __forceinline__ float4 fmax4(float4 a, float4 b) {
    return make_float4(fmaxf(a.x, b.x), fmaxf(a.y, b.y),
                       fmaxf(a.z, b.z), fmaxf(a.w, b.w));
}
__device__ __forceinline__ float4 ld4s(const float* p) {
    return *reinterpret_cast<const float4*>(p);
}

// 2 sliding maxes of window W over W+1 consecutive float4 rows at stride RSTR.
// Register-lean: only 3 float4 live during streaming.
template<int W>
__device__ __forceinline__ void colslide2(const float* __restrict__ base,
                                          float4* __restrict__ out) {
    if constexpr (W == 1) {
        out[0] = ld4s(base);
        out[1] = ld4s(base + RSTR);
    } else {
        float4 a0   = ld4s(base);
        float4 core = ld4s(base + RSTR);        // rows 1..W-1
        #pragma unroll
        for (int k = 2; k < W; k++) core = fmax4(core, ld4s(base + k * RSTR));
        float4 aW   = ld4s(base + W * RSTR);
        out[0] = fmax4(a0, core);
        out[1] = fmax4(core, aW);
    }
}

// ---------------------------------------------------------------------------
// Row pass over 38 real rows (608 quads, 5 warp-uniform iterations of 128
// threads). Just-in-time LDG per item (low live-reg count; latency covered by
// 36 warps/SM). Lanes 0-15 = one row, 16-31 = next; c = lane & 15.
// ---------------------------------------------------------------------------
template<int R>
__device__ __forceinline__ void row_pass(const float* __restrict__ xg,
                                         float* __restrict__ rowS,
                                         float* __restrict__ rowB,
                                         int grow0, int rs0) {
    const int t = threadIdx.x;
    const int c = t & 15;
    const unsigned FULL = 0xffffffffu;

    #pragma unroll
    for (int k = 0; k < 5; k++) {
        const int idx = t + (k << 7);
        if (idx < 608) {                       // warp-uniform guard
            const int row = idx >> 4;
            const float4 q = *reinterpret_cast<const float4*>(
                xg + (grow0 + row) * HW + (c << 2));

            float r[20];  // r[i] = col 4c - 8 + i; r[2..17] used (R<=5)
            r[8] = q.x; r[9] = q.y; r[10] = q.z; r[11] = q.w;
            r[4]  = __shfl_up_sync(FULL, q.x, 1);
            r[5]  = __shfl_up_sync(FULL, q.y, 1);
            r[6]  = __shfl_up_sync(FULL, q.z, 1);
            r[7]  = __shfl_up_sync(FULL, q.w, 1);
            r[2]  = __shfl_up_sync(FULL, q.z, 2);
            r[3]  = __shfl_up_sync(FULL, q.w, 2);
            r[12] = __shfl_down_sync(FULL, q.x, 1);
            r[13] = __shfl_down_sync(FULL, q.y, 1);
            r[14] = __shfl_down_sync(FULL, q.z, 1);
            r[15] = __shfl_down_sync(FULL, q.w, 1);
            r[16] = __shfl_down_sync(FULL, q.x, 2);
            r[17] = __shfl_down_sync(FULL, q.y, 2);
            if (c < 1)  { r[4] = r[5] = r[6] = r[7] = NEG_INF; }
            if (c < 2)  { r[2] = r[3] = NEG_INF; }
            if (c > 14) { r[12] = r[13] = r[14] = r[15] = NEG_INF; }
            if (c > 13) { r[16] = r[17] = NEG_INF; }

            float mS[4], mB[4];
            if constexpr (R == 0) {
                #pragma unroll
                for (int j = 0; j < 4; j++) mS[j] = r[8 + j];
            } else if constexpr (R == 1) {
                #pragma unroll
                for (int j = 0; j < 4; j++)
                    mS[j] = fmaxf(r[7 + j], fmaxf(r[8 + j], r[9 + j]));
            } else {
                float core = r[11 - R];
                #pragma unroll
                for (int u = 12 - R; u <= 8 + R; u++) core = fmaxf(core, r[u]);
                mS[0] = fmaxf(fmaxf(core, r[8 - R]),  fmaxf(r[9 - R],  r[10 - R]));
                mS[1] = fmaxf(fmaxf(core, r[9 - R]),  fmaxf(r[10 - R], r[9 + R]));
                mS[2] = fmaxf(fmaxf(core, r[10 - R]), fmaxf(r[9 + R],  r[10 + R]));
                mS[3] = fmaxf(fmaxf(core, r[9 + R]),  fmaxf(r[10 + R], r[11 + R]));
            }
            #pragma unroll
            for (int j = 0; j < 4; j++)
                mB[j] = fmaxf(mS[j], fmaxf(r[7 - R + j], r[9 + R + j]));

            const int ro = (rs0 + row) * RSTR + (c << 2);
            *reinterpret_cast<float4*>(rowS + ro) =
                make_float4(mS[0], mS[1], mS[2], mS[3]);
            *reinterpret_cast<float4*>(rowB + ro) =
                make_float4(mB[0], mB[1], mB[2], mB[3]);
        }
    }
}

// ---------------------------------------------------------------------------
// Column pass (after barrier): 4 output rows per thread, in 2-row groups to
// keep the live window at 3 float4. Residual folded immediately after stage S.
// Global row g -> srow yl + 6 (yl = local row).
// ---------------------------------------------------------------------------
template<int R>
__device__ __forceinline__ void col_pass(const float* __restrict__ xg,
                                         float* __restrict__ outg,
                                         const float* __restrict__ rowS,
                                         const float* __restrict__ rowB,
                                         float fb, int y0) {
    const int t = threadIdx.x;
    const int c4 = (t & 15) << 2;
    const int yl = (t >> 4) << 2;              // 0,4,...,28
    const float fs = 1.0f - fb;

    // ---- stage S: window 2R+1 over rowS ----
    float4 mS[4];
    colslide2<2 * R + 1>(rowS + (yl - R + 6) * RSTR + c4, mS);
    colslide2<2 * R + 1>(rowS + (yl + 2 - R + 6) * RSTR + c4, mS + 2);

    // fold residual immediately (mS and res die into part)
    float4 part[4];
    #pragma unroll
    for (int j = 0; j < 4; j++) {
        const float4 res = *reinterpret_cast<const float4*>(
            xg + (y0 + yl + j) * HW + c4);
        part[j].x = fmaf(fs, mS[j].x, res.x);
        part[j].y = fmaf(fs, mS[j].y, res.y);
        part[j].z = fmaf(fs, mS[j].z, res.z);
        part[j].w = fmaf(fs, mS[j].w, res.w);
    }

    // ---- stage B: window 2R+3 over rowB, blend + store per 2-row group ----
    {
        float4 mB[2];
        colslide2<2 * R + 3>(rowB + (yl - R - 1 + 6) * RSTR + c4, mB);
        #pragma unroll
        for (int j = 0; j < 2; j++) {
            float4 o;
            o.x = fmaf(fb, mB[j].x, part[j].x);
            o.y = fmaf(fb, mB[j].y, part[j].y);
            o.z = fmaf(fb, mB[j].z, part[j].z);
            o.w = fmaf(fb, mB[j].w, part[j].w);
            *reinterpret_cast<float4*>(outg + (y0 + yl + j) * HW + c4) = o;
        }
    }
    {
        float4 mB[2];
        colslide2<2 * R + 3>(rowB + (yl + 2 - R - 1 + 6) * RSTR + c4, mB);
        #pragma unroll
        for (int j = 0; j < 2; j++) {
            float4 o;
            o.x = fmaf(fb, mB[j].x, part[2 + j].x);
            o.y = fmaf(fb, mB[j].y, part[2 + j].y);
            o.z = fmaf(fb, mB[j].z, part[2 + j].z);
            o.w = fmaf(fb, mB[j].w, part[2 + j].w);
            *reinterpret_cast<float4*>(outg + (y0 + yl + 2 + j) * HW + c4) = o;
        }
    }
}

// ---------------------------------------------------------------------------
// Kernel 3: one CTA (128 threads) per half-plane, grid 8192, one barrier.
// Register-lean: target no spills under the (128,9) 56-reg cap.
// ---------------------------------------------------------------------------
__global__ __launch_bounds__(128, 9) void pool_kernel(const float* __restrict__ x,
                                                      float* __restrict__ out) {
    __shared__ float rowS[NSROW * RSTR];
    __shared__ float rowB[NSROW * RSTR];

    const int t = threadIdx.x;
    const int plane = blockIdx.x >> 1;
    const int half  = blockIdx.x & 1;
    const int y0    = half ? 32 : 0;   // first output row
    const int grow0 = half ? 26 : 0;   // first loaded input row
    const int rs0   = half ? 0  : 6;   // srow of first real row
    const int pad0  = half ? 38 : 0;   // first pad srow

    const float* xg = x + (size_t)plane * PLANE_ELEMS;
    float* outg = out + (size_t)plane * PLANE_ELEMS;
    const int   r  = g_q[plane];
    const float fb = g_fb[plane];

    // fill 6 pad srows of each array with -inf
    #pragma unroll
    for (int i = t; i < 12 * 64; i += 128) {
        const int pr = i >> 6, cc = i & 63;
        if (pr < 6) rowS[(pad0 + pr) * RSTR + cc] = NEG_INF;
        else        rowB[(pad0 + pr - 6) * RSTR + cc] = NEG_INF;
    }

    switch (r) {
        case 0: row_pass<0>(xg, rowS, rowB, grow0, rs0); __syncthreads();
                col_pass<0>(xg, outg, rowS, rowB, fb, y0); break;
        case 1: row_pass<1>(xg, rowS, rowB, grow0, rs0); __syncthreads();
                col_pass<1>(xg, outg, rowS, rowB, fb, y0); break;
        case 2: row_pass<2>(xg, rowS, rowB, grow0, rs0); __syncthreads();
                col_pass<2>(xg, outg, rowS, rowB, fb, y0); break;
        case 3: row_pass<3>(xg, rowS, rowB, grow0, rs0); __syncthreads();
                col_pass<3>(xg, outg, rowS, rowB, fb, y0); break;
        case 4: row_pass<4>(xg, rowS, rowB, grow0, rs0); __syncthreads();
                col_pass<4>(xg, outg, rowS, rowB, fb, y0); break;
        default: row_pass<5>(xg, rowS, rowB, grow0, rs0); __syncthreads();
                col_pass<5>(xg, outg, rowS, rowB, fb, y0); break;
    }
}

// ---------------------------------------------------------------------------
extern "C" void kernel_launch(void* const* d_in, const int* in_sizes, int n_in,
                              void* d_out, int out_size) {
    const float* x  = (const float*)d_in[0];
    const float* w1 = (const float*)d_in[1];
    const float* b1 = (const float*)d_in[2];
    const float* w2 = (const float*)d_in[3];
    const float* b2 = (const float*)d_in[4];
    float* out = (float*)d_out;

    gap_kernel<<<NPLANES, 256>>>(x);
    se_kernel<<<8, 512>>>(w1, b1, w2, b2);
    pool_kernel<<<NPLANES * 2, 128>>>(x, out);
}

// round 13
// speedup vs baseline: 1.0065x; 1.0065x over previous
#include <cuda_runtime.h>
#include <math.h>
#include <float.h>

// Shapes (fixed): x [8,512,64,64] f32; w1 [32,512]; b1 [32]; w2 [512,32]; b2 [512]
#define NPLANES 4096
#define PLANE_ELEMS 4096
#define HW 64
#define NEG_INF (-FLT_MAX)

// Per-CTA smem: rowS/rowB for 44 srows (32 output rows + 6 halo/pad each side),
// stride 64. srow s <-> global row (s - 6 + y0).
#define RSTR 64
#define NSROW 44

// Scratch (no allocations allowed -> device globals)
__device__ float g_gap[NPLANES];
__device__ int   g_q[NPLANES];
__device__ float g_fb[NPLANES];

// ---------------------------------------------------------------------------
// Kernel 1: per-plane mean
// ---------------------------------------------------------------------------
__global__ __launch_bounds__(256) void gap_kernel(const float* __restrict__ x) {
    const int plane = blockIdx.x;
    const float4* __restrict__ p =
        reinterpret_cast<const float4*>(x + (size_t)plane * PLANE_ELEMS);

    float sum = 0.f;
    #pragma unroll 4
    for (int i = threadIdx.x; i < PLANE_ELEMS / 4; i += 256) {
        float4 v = p[i];
        sum += (v.x + v.y) + (v.z + v.w);
    }
    #pragma unroll
    for (int off = 16; off > 0; off >>= 1)
        sum += __shfl_down_sync(0xffffffffu, sum, off);

    __shared__ float warp_sums[8];
    const int lane = threadIdx.x & 31, wid = threadIdx.x >> 5;
    if (lane == 0) warp_sums[wid] = sum;
    __syncthreads();
    if (threadIdx.x == 0) {
        float t = 0.f;
        #pragma unroll
        for (int i = 0; i < 8; i++) t += warp_sums[i];
        g_gap[plane] = t * (1.0f / (float)PLANE_ELEMS);
    }
}

// ---------------------------------------------------------------------------
// Kernel 2: SE bottleneck + routing
// ---------------------------------------------------------------------------
__global__ __launch_bounds__(512) void se_kernel(const float* __restrict__ w1,
                                                 const float* __restrict__ b1,
                                                 const float* __restrict__ w2,
                                                 const float* __restrict__ b2) {
    __shared__ float sgap[512];
    __shared__ float shmid[32];
    const int b = blockIdx.x;
    const int t = threadIdx.x;

    sgap[t] = g_gap[b * 512 + t];
    __syncthreads();

    if (t < 32) {
        float acc = b1[t];
        const float* wr = w1 + t * 512;
        #pragma unroll 8
        for (int k = 0; k < 512; k++) acc = fmaf(sgap[k], wr[k], acc);
        shmid[t] = fmaxf(acc, 0.f);
    }
    __syncthreads();

    float acc = b2[t];
    const float* wr = w2 + t * 32;
    #pragma unroll
    for (int j = 0; j < 32; j++) acc = fmaf(shmid[j], wr[j], acc);
    const float s = fmaxf(acc, 0.f);

    int q = (int)floorf(s);
    q = min(max(q, 0), 5);
    const int plane = b * 512 + t;
    g_q[plane]  = q;
    g_fb[plane] = s - (float)q;
}

// ---------------------------------------------------------------------------
__device__ __forceinline__ float4 fmax4(float4 a, float4 b) {
    return make_float4(fmaxf(a.x, b.x), fmaxf(a.y, b.y),
                       fmaxf(a.z, b.z), fmaxf(a.w, b.w));
}
__device__ __forceinline__ float4 ld4s(const float* p) {
    return *reinterpret_cast<const float4*>(p);
}

// 4 sliding maxes of window W over float4 rows in smem at stride RSTR
// (shared-core streaming: W+3 loads per 4 outputs).
template<int W>
__device__ __forceinline__ void colslide(const float* __restrict__ base,
                                         float4 out[4]) {
    if constexpr (W == 1) {
        #pragma unroll
        for (int j = 0; j < 4; j++) out[j] = ld4s(base + j * RSTR);
    } else if constexpr (W <= 3) {
        float4 a[W + 3];
        #pragma unroll
        for (int k = 0; k < W + 3; k++) a[k] = ld4s(base + k * RSTR);
        #pragma unroll
        for (int j = 0; j < 4; j++) {
            float4 m = a[j];
            #pragma unroll
            for (int u = 1; u < W; u++) m = fmax4(m, a[j + u]);
            out[j] = m;
        }
    } else {
        float4 a0 = ld4s(base), a1 = ld4s(base + RSTR), a2 = ld4s(base + 2 * RSTR);
        float4 core = ld4s(base + 3 * RSTR);
        #pragma unroll
        for (int k = 4; k < W; k++) core = fmax4(core, ld4s(base + k * RSTR));
        float4 aW  = ld4s(base + W * RSTR);
        float4 aW1 = ld4s(base + (W + 1) * RSTR);
        float4 aW2 = ld4s(base + (W + 2) * RSTR);
        out[0] = fmax4(fmax4(core, a0), fmax4(a1, a2));
        out[1] = fmax4(fmax4(core, a1), fmax4(a2, aW));
        out[2] = fmax4(fmax4(core, a2), fmax4(aW, aW1));
        out[3] = fmax4(fmax4(core, aW), fmax4(aW1, aW2));
    }
}

// ---------------------------------------------------------------------------
// Row pass in 8-wide strips: thread owns cols [8s, 8s+8) of one row.
// 38 rows x 8 strips = 304 items; 3 iterations of 128 threads (all lanes run
// the shuffles; stores predicated). Neighbor cols via lane+-1 shuffles.
// a[i] = value at local col i-6 (i = 0..19); needs R+1 <= 6. Strip s=0 / s=7
// mask left / right halo to -inf (SAME padding).
// ---------------------------------------------------------------------------
template<int R>
__device__ __forceinline__ void row_pass(const float* __restrict__ xg,
                                         float* __restrict__ rowS,
                                         float* __restrict__ rowB,
                                         int grow0, int rs0) {
    const int t = threadIdx.x;
    const unsigned FULL = 0xffffffffu;

    #pragma unroll
    for (int k = 0; k < 3; k++) {
        const int idx = t + (k << 7);
        const int s   = idx & 7;
        int row = idx >> 3;
        if (row > 37) row = 37;                 // dup work, store masked

        float a[20];
        {
            const float* rp = xg + (grow0 + row) * HW + (s << 3);
            *reinterpret_cast<float4*>(&a[6])  = *reinterpret_cast<const float4*>(rp);
            *reinterpret_cast<float4*>(&a[10]) = *reinterpret_cast<const float4*>(rp + 4);
        }
        // left halo: lane-1's cols [2..7] -> local cols -6..-1 = a[0..5]
        a[0] = __shfl_up_sync(FULL, a[8],  1);
        a[1] = __shfl_up_sync(FULL, a[9],  1);
        a[2] = __shfl_up_sync(FULL, a[10], 1);
        a[3] = __shfl_up_sync(FULL, a[11], 1);
        a[4] = __shfl_up_sync(FULL, a[12], 1);
        a[5] = __shfl_up_sync(FULL, a[13], 1);
        // right halo: lane+1's cols [0..5] -> local cols 8..13 = a[14..19]
        a[14] = __shfl_down_sync(FULL, a[6],  1);
        a[15] = __shfl_down_sync(FULL, a[7],  1);
        a[16] = __shfl_down_sync(FULL, a[8],  1);
        a[17] = __shfl_down_sync(FULL, a[9],  1);
        a[18] = __shfl_down_sync(FULL, a[10], 1);
        a[19] = __shfl_down_sync(FULL, a[11], 1);
        if (s == 0) { a[0] = a[1] = a[2] = a[3] = a[4] = a[5] = NEG_INF; }
        if (s == 7) { a[14] = a[15] = a[16] = a[17] = a[18] = a[19] = NEG_INF; }

        float mS[8], mB[8];
        if constexpr (R == 0) {
            #pragma unroll
            for (int j = 0; j < 8; j++) mS[j] = a[6 + j];
        } else if constexpr (R == 1) {
            #pragma unroll
            for (int j = 0; j < 8; j++)
                mS[j] = fmaxf(a[5 + j], fmaxf(a[6 + j], a[7 + j]));
        } else {
            // group A: outputs 0..3, core a[9-R .. 6+R]
            float coreA = a[9 - R];
            #pragma unroll
            for (int u = 10 - R; u <= 6 + R; u++) coreA = fmaxf(coreA, a[u]);
            mS[0] = fmaxf(fmaxf(coreA, a[6 - R]), fmaxf(a[7 - R], a[8 - R]));
            mS[1] = fmaxf(fmaxf(coreA, a[7 - R]), fmaxf(a[8 - R], a[7 + R]));
            mS[2] = fmaxf(fmaxf(coreA, a[8 - R]), fmaxf(a[7 + R], a[8 + R]));
            mS[3] = fmaxf(fmaxf(coreA, a[7 + R]), fmaxf(a[8 + R], a[9 + R]));
            // group B: outputs 4..7, core a[13-R .. 10+R]
            float coreB = a[13 - R];
            #pragma unroll
            for (int u = 14 - R; u <= 10 + R; u++) coreB = fmaxf(coreB, a[u]);
            mS[4] = fmaxf(fmaxf(coreB, a[10 - R]), fmaxf(a[11 - R], a[12 - R]));
            mS[5] = fmaxf(fmaxf(coreB, a[11 - R]), fmaxf(a[12 - R], a[11 + R]));
            mS[6] = fmaxf(fmaxf(coreB, a[12 - R]), fmaxf(a[11 + R], a[12 + R]));
            mS[7] = fmaxf(fmaxf(coreB, a[11 + R]), fmaxf(a[12 + R], a[13 + R]));
        }
        #pragma unroll
        for (int j = 0; j < 8; j++)
            mB[j] = fmaxf(mS[j], fmaxf(a[5 + j - R], a[7 + j + R]));

        if (idx < 304) {
            const int ro = (rs0 + row) * RSTR + (s << 3);
            *reinterpret_cast<float4*>(rowS + ro)     = make_float4(mS[0], mS[1], mS[2], mS[3]);
            *reinterpret_cast<float4*>(rowS + ro + 4) = make_float4(mS[4], mS[5], mS[6], mS[7]);
            *reinterpret_cast<float4*>(rowB + ro)     = make_float4(mB[0], mB[1], mB[2], mB[3]);
            *reinterpret_cast<float4*>(rowB + ro + 4) = make_float4(mB[4], mB[5], mB[6], mB[7]);
        }
    }
}

// ---------------------------------------------------------------------------
// Column pass (after barrier): thread owns 4 rows x 4 cols; shared-core
// streaming windows. Global row g -> srow (local row + 6).
// ---------------------------------------------------------------------------
template<int R>
__device__ __forceinline__ void col_pass(const float* __restrict__ xg,
                                         float* __restrict__ outg,
                                         const float* __restrict__ rowS,
                                         const float* __restrict__ rowB,
                                         float fb, int y0) {
    const int t = threadIdx.x;
    const int c4 = (t & 15) << 2;
    const int yl = (t >> 4) << 2;              // 0,4,...,28
    const float fs = 1.0f - fb;

    float4 part[4];
    {
        float4 mS4[4];
        colslide<2 * R + 1>(rowS + (yl - R + 6) * RSTR + c4, mS4);
        #pragma unroll
        for (int j = 0; j < 4; j++) {
            const float4 res = *reinterpret_cast<const float4*>(
                xg + (y0 + yl + j) * HW + c4);
            part[j].x = fmaf(fs, mS4[j].x, res.x);
            part[j].y = fmaf(fs, mS4[j].y, res.y);
            part[j].z = fmaf(fs, mS4[j].z, res.z);
            part[j].w = fmaf(fs, mS4[j].w, res.w);
        }
    }
    {
        float4 mB4[4];
        colslide<2 * R + 3>(rowB + (yl - R - 1 + 6) * RSTR + c4, mB4);
        #pragma unroll
        for (int j = 0; j < 4; j++) {
            float4 o;
            o.x = fmaf(fb, mB4[j].x, part[j].x);
            o.y = fmaf(fb, mB4[j].y, part[j].y);
            o.z = fmaf(fb, mB4[j].z, part[j].z);
            o.w = fmaf(fb, mB4[j].w, part[j].w);
            *reinterpret_cast<float4*>(outg + (y0 + yl + j) * HW + c4) = o;
        }
    }
}

// ---------------------------------------------------------------------------
// Kernel 3: one CTA (128 threads) per half-plane, grid 8192, one barrier.
// ---------------------------------------------------------------------------
__global__ __launch_bounds__(128, 8) void pool_kernel(const float* __restrict__ x,
                                                      float* __restrict__ out) {
    __shared__ float rowS[NSROW * RSTR];
    __shared__ float rowB[NSROW * RSTR];

    const int t = threadIdx.x;
    const int plane = blockIdx.x >> 1;
    const int half  = blockIdx.x & 1;
    const int y0    = half ? 32 : 0;   // first output row
    const int grow0 = half ? 26 : 0;   // first loaded input row
    const int rs0   = half ? 0  : 6;   // srow of first real row
    const int pad0  = half ? 38 : 0;   // first pad srow

    const float* xg = x + (size_t)plane * PLANE_ELEMS;
    float* outg = out + (size_t)plane * PLANE_ELEMS;
    const int   r  = g_q[plane];
    const float fb = g_fb[plane];

    // fill 6 pad srows of each array with -inf
    #pragma unroll
    for (int i = t; i < 12 * 64; i += 128) {
        const int pr = i >> 6, cc = i & 63;
        if (pr < 6) rowS[(pad0 + pr) * RSTR + cc] = NEG_INF;
        else        rowB[(pad0 + pr - 6) * RSTR + cc] = NEG_INF;
    }

    switch (r) {
        case 0: row_pass<0>(xg, rowS, rowB, grow0, rs0); __syncthreads();
                col_pass<0>(xg, outg, rowS, rowB, fb, y0); break;
        case 1: row_pass<1>(xg, rowS, rowB, grow0, rs0); __syncthreads();
                col_pass<1>(xg, outg, rowS, rowB, fb, y0); break;
        case 2: row_pass<2>(xg, rowS, rowB, grow0, rs0); __syncthreads();
                col_pass<2>(xg, outg, rowS, rowB, fb, y0); break;
        case 3: row_pass<3>(xg, rowS, rowB, grow0, rs0); __syncthreads();
                col_pass<3>(xg, outg, rowS, rowB, fb, y0); break;
        case 4: row_pass<4>(xg, rowS, rowB, grow0, rs0); __syncthreads();
                col_pass<4>(xg, outg, rowS, rowB, fb, y0); break;
        default: row_pass<5>(xg, rowS, rowB, grow0, rs0); __syncthreads();
                col_pass<5>(xg, outg, rowS, rowB, fb, y0); break;
    }
}

// ---------------------------------------------------------------------------
extern "C" void kernel_launch(void* const* d_in, const int* in_sizes, int n_in,
                              void* d_out, int out_size) {
    const float* x  = (const float*)d_in[0];
    const float* w1 = (const float*)d_in[1];
    const float* b1 = (const float*)d_in[2];
    const float* w2 = (const float*)d_in[3];
    const float* b2 = (const float*)d_in[4];
    float* out = (float*)d_out;

    gap_kernel<<<NPLANES, 256>>>(x);
    se_kernel<<<8, 512>>>(w1, b1, w2, b2);
    pool_kernel<<<NPLANES * 2, 128>>>(x, out);
}

// round 14
// speedup vs baseline: 1.0269x; 1.0203x over previous
#include <cuda_runtime.h>
#include <math.h>
#include <float.h>

// Shapes (fixed): x [8,512,64,64] f32; w1 [32,512]; b1 [32]; w2 [512,32]; b2 [512]
#define NPLANES 4096
#define PLANE_ELEMS 4096
#define HW 64
#define NEG_INF (-FLT_MAX)

// Per-CTA smem: rowS/rowB for 44 srows (32 output rows + 6 halo/pad each side),
// stride 64. srow s <-> global row (s - 6 + y0).
#define RSTR 64
#define NSROW 44

// Scratch (no allocations allowed -> device globals)
__device__ float  g_gap[NPLANES];
__device__ float2 g_route[NPLANES];   // .x = (float)q, .y = frac_b

// ---------------------------------------------------------------------------
// Kernel 1: per-plane mean. One block = TWO planes -> 8 independent LDG.128
// per thread (MLP 8) to push DRAM utilization.
// ---------------------------------------------------------------------------
__global__ __launch_bounds__(256) void gap_kernel(const float* __restrict__ x) {
    const int p0 = blockIdx.x << 1;
    const float4* __restrict__ pa =
        reinterpret_cast<const float4*>(x + (size_t)p0 * PLANE_ELEMS);
    const float4* __restrict__ pb = pa + (PLANE_ELEMS / 4);

    float sa = 0.f, sb = 0.f;
    #pragma unroll
    for (int k = 0; k < 4; k++) {
        const int i = threadIdx.x + (k << 8);
        const float4 a = pa[i];
        const float4 b = pb[i];
        sa += (a.x + a.y) + (a.z + a.w);
        sb += (b.x + b.y) + (b.z + b.w);
    }
    #pragma unroll
    for (int off = 16; off > 0; off >>= 1) {
        sa += __shfl_down_sync(0xffffffffu, sa, off);
        sb += __shfl_down_sync(0xffffffffu, sb, off);
    }
    __shared__ float wsum[2][8];
    const int lane = threadIdx.x & 31, wid = threadIdx.x >> 5;
    if (lane == 0) { wsum[0][wid] = sa; wsum[1][wid] = sb; }
    __syncthreads();
    if (threadIdx.x < 2) {
        float t = 0.f;
        #pragma unroll
        for (int i = 0; i < 8; i++) t += wsum[threadIdx.x][i];
        g_gap[p0 + threadIdx.x] = t * (1.0f / (float)PLANE_ELEMS);
    }
}

// ---------------------------------------------------------------------------
// Kernel 2: SE bottleneck + routing (one block per batch image)
// ---------------------------------------------------------------------------
__global__ __launch_bounds__(512) void se_kernel(const float* __restrict__ w1,
                                                 const float* __restrict__ b1,
                                                 const float* __restrict__ w2,
                                                 const float* __restrict__ b2) {
    __shared__ float sgap[512];
    __shared__ float shmid[32];
    const int b = blockIdx.x;
    const int t = threadIdx.x;

    sgap[t] = g_gap[b * 512 + t];
    __syncthreads();

    if (t < 32) {
        float acc = b1[t];
        const float* wr = w1 + t * 512;
        #pragma unroll 8
        for (int k = 0; k < 512; k++) acc = fmaf(sgap[k], wr[k], acc);
        shmid[t] = fmaxf(acc, 0.f);
    }
    __syncthreads();

    float acc = b2[t];
    const float* wr = w2 + t * 32;
    #pragma unroll
    for (int j = 0; j < 32; j++) acc = fmaf(shmid[j], wr[j], acc);
    const float s = fmaxf(acc, 0.f);

    int q = (int)floorf(s);
    q = min(max(q, 0), 5);
    g_route[b * 512 + t] = make_float2((float)q, s - (float)q);
}

// ---------------------------------------------------------------------------
__device__ __forceinline__ float4 fmax4(float4 a, float4 b) {
    return make_float4(fmaxf(a.x, b.x), fmaxf(a.y, b.y),
                       fmaxf(a.z, b.z), fmaxf(a.w, b.w));
}
__device__ __forceinline__ float4 ld4s(const float* p) {
    return *reinterpret_cast<const float4*>(p);
}

// 4 sliding maxes of window W over float4 rows in smem at stride RSTR
// (shared-core streaming: W+3 loads per 4 outputs).
template<int W>
__device__ __forceinline__ void colslide(const float* __restrict__ base,
                                         float4 out[4]) {
    if constexpr (W == 1) {
        #pragma unroll
        for (int j = 0; j < 4; j++) out[j] = ld4s(base + j * RSTR);
    } else if constexpr (W <= 3) {
        float4 a[W + 3];
        #pragma unroll
        for (int k = 0; k < W + 3; k++) a[k] = ld4s(base + k * RSTR);
        #pragma unroll
        for (int j = 0; j < 4; j++) {
            float4 m = a[j];
            #pragma unroll
            for (int u = 1; u < W; u++) m = fmax4(m, a[j + u]);
            out[j] = m;
        }
    } else {
        float4 a0 = ld4s(base), a1 = ld4s(base + RSTR), a2 = ld4s(base + 2 * RSTR);
        float4 core = ld4s(base + 3 * RSTR);
        #pragma unroll
        for (int k = 4; k < W; k++) core = fmax4(core, ld4s(base + k * RSTR));
        float4 aW  = ld4s(base + W * RSTR);
        float4 aW1 = ld4s(base + (W + 1) * RSTR);
        float4 aW2 = ld4s(base + (W + 2) * RSTR);
        out[0] = fmax4(fmax4(core, a0), fmax4(a1, a2));
        out[1] = fmax4(fmax4(core, a1), fmax4(a2, aW));
        out[2] = fmax4(fmax4(core, a2), fmax4(aW, aW1));
        out[3] = fmax4(fmax4(core, aW), fmax4(aW1, aW2));
    }
}

// ---------------------------------------------------------------------------
// Row pass in 8-wide strips: thread owns cols [8s, 8s+8) of one row.
// 38 rows x 8 strips = 304 items; 3 warp-uniform iterations of 128 threads.
// a[i] = value at local col i-6; strips 0/7 mask halo to -inf (SAME padding).
// ---------------------------------------------------------------------------
template<int R>
__device__ __forceinline__ void row_pass(const float* __restrict__ xg,
                                         float* __restrict__ rowS,
                                         float* __restrict__ rowB,
                                         int grow0, int rs0) {
    const int t = threadIdx.x;
    const unsigned FULL = 0xffffffffu;

    #pragma unroll
    for (int k = 0; k < 3; k++) {
        const int idx = t + (k << 7);
        const int s   = idx & 7;
        int row = idx >> 3;
        if (row > 37) row = 37;                 // dup work, store masked

        float a[20];
        {
            const float* rp = xg + (grow0 + row) * HW + (s << 3);
            *reinterpret_cast<float4*>(&a[6])  = *reinterpret_cast<const float4*>(rp);
            *reinterpret_cast<float4*>(&a[10]) = *reinterpret_cast<const float4*>(rp + 4);
        }
        a[0] = __shfl_up_sync(FULL, a[8],  1);
        a[1] = __shfl_up_sync(FULL, a[9],  1);
        a[2] = __shfl_up_sync(FULL, a[10], 1);
        a[3] = __shfl_up_sync(FULL, a[11], 1);
        a[4] = __shfl_up_sync(FULL, a[12], 1);
        a[5] = __shfl_up_sync(FULL, a[13], 1);
        a[14] = __shfl_down_sync(FULL, a[6],  1);
        a[15] = __shfl_down_sync(FULL, a[7],  1);
        a[16] = __shfl_down_sync(FULL, a[8],  1);
        a[17] = __shfl_down_sync(FULL, a[9],  1);
        a[18] = __shfl_down_sync(FULL, a[10], 1);
        a[19] = __shfl_down_sync(FULL, a[11], 1);
        if (s == 0) { a[0] = a[1] = a[2] = a[3] = a[4] = a[5] = NEG_INF; }
        if (s == 7) { a[14] = a[15] = a[16] = a[17] = a[18] = a[19] = NEG_INF; }

        float mS[8], mB[8];
        if constexpr (R == 0) {
            #pragma unroll
            for (int j = 0; j < 8; j++) mS[j] = a[6 + j];
        } else if constexpr (R == 1) {
            #pragma unroll
            for (int j = 0; j < 8; j++)
                mS[j] = fmaxf(a[5 + j], fmaxf(a[6 + j], a[7 + j]));
        } else {
            float coreA = a[9 - R];
            #pragma unroll
            for (int u = 10 - R; u <= 6 + R; u++) coreA = fmaxf(coreA, a[u]);
            mS[0] = fmaxf(fmaxf(coreA, a[6 - R]), fmaxf(a[7 - R], a[8 - R]));
            mS[1] = fmaxf(fmaxf(coreA, a[7 - R]), fmaxf(a[8 - R], a[7 + R]));
            mS[2] = fmaxf(fmaxf(coreA, a[8 - R]), fmaxf(a[7 + R], a[8 + R]));
            mS[3] = fmaxf(fmaxf(coreA, a[7 + R]), fmaxf(a[8 + R], a[9 + R]));
            float coreB = a[13 - R];
            #pragma unroll
            for (int u = 14 - R; u <= 10 + R; u++) coreB = fmaxf(coreB, a[u]);
            mS[4] = fmaxf(fmaxf(coreB, a[10 - R]), fmaxf(a[11 - R], a[12 - R]));
            mS[5] = fmaxf(fmaxf(coreB, a[11 - R]), fmaxf(a[12 - R], a[11 + R]));
            mS[6] = fmaxf(fmaxf(coreB, a[12 - R]), fmaxf(a[11 + R], a[12 + R]));
            mS[7] = fmaxf(fmaxf(coreB, a[11 + R]), fmaxf(a[12 + R], a[13 + R]));
        }
        #pragma unroll
        for (int j = 0; j < 8; j++)
            mB[j] = fmaxf(mS[j], fmaxf(a[5 + j - R], a[7 + j + R]));

        if (idx < 304) {
            const int ro = (rs0 + row) * RSTR + (s << 3);
            *reinterpret_cast<float4*>(rowS + ro)     = make_float4(mS[0], mS[1], mS[2], mS[3]);
            *reinterpret_cast<float4*>(rowS + ro + 4) = make_float4(mS[4], mS[5], mS[6], mS[7]);
            *reinterpret_cast<float4*>(rowB + ro)     = make_float4(mB[0], mB[1], mB[2], mB[3]);
            *reinterpret_cast<float4*>(rowB + ro + 4) = make_float4(mB[4], mB[5], mB[6], mB[7]);
        }
    }
}

// ---------------------------------------------------------------------------
// Column pass (after barrier): thread owns 4 rows x 4 cols; shared-core
// streaming windows. Global row g -> srow (local row + 6).
// ---------------------------------------------------------------------------
template<int R>
__device__ __forceinline__ void col_pass(const float* __restrict__ xg,
                                         float* __restrict__ outg,
                                         const float* __restrict__ rowS,
                                         const float* __restrict__ rowB,
                                         float fb, int y0) {
    const int t = threadIdx.x;
    const int c4 = (t & 15) << 2;
    const int yl = (t >> 4) << 2;              // 0,4,...,28
    const float fs = 1.0f - fb;

    float4 part[4];
    {
        float4 mS4[4];
        colslide<2 * R + 1>(rowS + (yl - R + 6) * RSTR + c4, mS4);
        #pragma unroll
        for (int j = 0; j < 4; j++) {
            const float4 res = *reinterpret_cast<const float4*>(
                xg + (y0 + yl + j) * HW + c4);
            part[j].x = fmaf(fs, mS4[j].x, res.x);
            part[j].y = fmaf(fs, mS4[j].y, res.y);
            part[j].z = fmaf(fs, mS4[j].z, res.z);
            part[j].w = fmaf(fs, mS4[j].w, res.w);
        }
    }
    {
        float4 mB4[4];
        colslide<2 * R + 3>(rowB + (yl - R - 1 + 6) * RSTR + c4, mB4);
        #pragma unroll
        for (int j = 0; j < 4; j++) {
            float4 o;
            o.x = fmaf(fb, mB4[j].x, part[j].x);
            o.y = fmaf(fb, mB4[j].y, part[j].y);
            o.z = fmaf(fb, mB4[j].z, part[j].z);
            o.w = fmaf(fb, mB4[j].w, part[j].w);
            *reinterpret_cast<float4*>(outg + (y0 + yl + j) * HW + c4) = o;
        }
    }
}

// ---------------------------------------------------------------------------
// Kernel 3: one CTA (128 threads) per half-plane, grid 8192, one barrier.
// ---------------------------------------------------------------------------
__global__ __launch_bounds__(128, 8) void pool_kernel(const float* __restrict__ x,
                                                      float* __restrict__ out) {
    __shared__ float rowS[NSROW * RSTR];
    __shared__ float rowB[NSROW * RSTR];

    const int t = threadIdx.x;
    const int plane = blockIdx.x >> 1;
    const int half  = blockIdx.x & 1;
    const int y0    = half ? 32 : 0;   // first output row
    const int grow0 = half ? 26 : 0;   // first loaded input row
    const int rs0   = half ? 0  : 6;   // srow of first real row
    const int pad0  = half ? 38 : 0;   // first pad srow

    const float* xg = x + (size_t)plane * PLANE_ELEMS;
    float* outg = out + (size_t)plane * PLANE_ELEMS;
    const float2 route = g_route[plane];   // one LDG.64
    const int   r  = (int)route.x;
    const float fb = route.y;

    // fill 6 pad srows of each array with -inf
    #pragma unroll
    for (int i = t; i < 12 * 64; i += 128) {
        const int pr = i >> 6, cc = i & 63;
        if (pr < 6) rowS[(pad0 + pr) * RSTR + cc] = NEG_INF;
        else        rowB[(pad0 + pr - 6) * RSTR + cc] = NEG_INF;
    }

    switch (r) {
        case 0: row_pass<0>(xg, rowS, rowB, grow0, rs0); __syncthreads();
                col_pass<0>(xg, outg, rowS, rowB, fb, y0); break;
        case 1: row_pass<1>(xg, rowS, rowB, grow0, rs0); __syncthreads();
                col_pass<1>(xg, outg, rowS, rowB, fb, y0); break;
        case 2: row_pass<2>(xg, rowS, rowB, grow0, rs0); __syncthreads();
                col_pass<2>(xg, outg, rowS, rowB, fb, y0); break;
        case 3: row_pass<3>(xg, rowS, rowB, grow0, rs0); __syncthreads();
                col_pass<3>(xg, outg, rowS, rowB, fb, y0); break;
        case 4: row_pass<4>(xg, rowS, rowB, grow0, rs0); __syncthreads();
                col_pass<4>(xg, outg, rowS, rowB, fb, y0); break;
        default: row_pass<5>(xg, rowS, rowB, grow0, rs0); __syncthreads();
                col_pass<5>(xg, outg, rowS, rowB, fb, y0); break;
    }
}

// ---------------------------------------------------------------------------
extern "C" void kernel_launch(void* const* d_in, const int* in_sizes, int n_in,
                              void* d_out, int out_size) {
    const float* x  = (const float*)d_in[0];
    const float* w1 = (const float*)d_in[1];
    const float* b1 = (const float*)d_in[2];
    const float* w2 = (const float*)d_in[3];
    const float* b2 = (const float*)d_in[4];
    float* out = (float*)d_out;

    gap_kernel<<<NPLANES / 2, 256>>>(x);
    se_kernel<<<8, 512>>>(w1, b1, w2, b2);
    pool_kernel<<<NPLANES * 2, 128>>>(x, out);
}

// round 15
// speedup vs baseline: 1.0816x; 1.0532x over previous
#include <cuda_runtime.h>
#include <math.h>
#include <float.h>

// Shapes (fixed): x [8,512,64,64] f32; w1 [32,512]; b1 [32]; w2 [512,32]; b2 [512]
#define NPLANES 4096
#define PLANE_ELEMS 4096
#define HW 64
#define NEG_INF (-FLT_MAX)

// Per-CTA smem: rowS/rowB for a FULL plane: 76 srows (64 real rows at srow
// 6..69, 6 -inf pad rows each side), stride 64.
#define RSTR 64
#define NSROW 76

// Scratch (no allocations allowed -> device globals)
__device__ float  g_gap[NPLANES];
__device__ float2 g_route[NPLANES];   // .x = (float)q, .y = frac_b

// ---------------------------------------------------------------------------
// Kernel 1: per-plane mean (two planes per block; at its read ceiling)
// ---------------------------------------------------------------------------
__global__ __launch_bounds__(256) void gap_kernel(const float* __restrict__ x) {
    const int p0 = blockIdx.x << 1;
    const float4* __restrict__ pa =
        reinterpret_cast<const float4*>(x + (size_t)p0 * PLANE_ELEMS);
    const float4* __restrict__ pb = pa + (PLANE_ELEMS / 4);

    float sa = 0.f, sb = 0.f;
    #pragma unroll
    for (int k = 0; k < 4; k++) {
        const int i = threadIdx.x + (k << 8);
        const float4 a = pa[i];
        const float4 b = pb[i];
        sa += (a.x + a.y) + (a.z + a.w);
        sb += (b.x + b.y) + (b.z + b.w);
    }
    #pragma unroll
    for (int off = 16; off > 0; off >>= 1) {
        sa += __shfl_down_sync(0xffffffffu, sa, off);
        sb += __shfl_down_sync(0xffffffffu, sb, off);
    }
    __shared__ float wsum[2][8];
    const int lane = threadIdx.x & 31, wid = threadIdx.x >> 5;
    if (lane == 0) { wsum[0][wid] = sa; wsum[1][wid] = sb; }
    __syncthreads();
    if (threadIdx.x < 2) {
        float t = 0.f;
        #pragma unroll
        for (int i = 0; i < 8; i++) t += wsum[threadIdx.x][i];
        g_gap[p0 + threadIdx.x] = t * (1.0f / (float)PLANE_ELEMS);
    }
}

// ---------------------------------------------------------------------------
// Kernel 2: SE bottleneck + routing (one block per batch image)
// ---------------------------------------------------------------------------
__global__ __launch_bounds__(512) void se_kernel(const float* __restrict__ w1,
                                                 const float* __restrict__ b1,
                                                 const float* __restrict__ w2,
                                                 const float* __restrict__ b2) {
    __shared__ float sgap[512];
    __shared__ float shmid[32];
    const int b = blockIdx.x;
    const int t = threadIdx.x;

    sgap[t] = g_gap[b * 512 + t];
    __syncthreads();

    if (t < 32) {
        float acc = b1[t];
        const float* wr = w1 + t * 512;
        #pragma unroll 8
        for (int k = 0; k < 512; k++) acc = fmaf(sgap[k], wr[k], acc);
        shmid[t] = fmaxf(acc, 0.f);
    }
    __syncthreads();

    float acc = b2[t];
    const float* wr = w2 + t * 32;
    #pragma unroll
    for (int j = 0; j < 32; j++) acc = fmaf(shmid[j], wr[j], acc);
    const float s = fmaxf(acc, 0.f);

    int q = (int)floorf(s);
    q = min(max(q, 0), 5);
    g_route[b * 512 + t] = make_float2((float)q, s - (float)q);
}

// ---------------------------------------------------------------------------
__device__ __forceinline__ float4 fmax4(float4 a, float4 b) {
    return make_float4(fmaxf(a.x, b.x), fmaxf(a.y, b.y),
                       fmaxf(a.z, b.z), fmaxf(a.w, b.w));
}
__device__ __forceinline__ float4 ld4s(const float* p) {
    return *reinterpret_cast<const float4*>(p);
}

// 4 sliding maxes of window W over float4 rows in smem at stride RSTR
// (shared-core streaming: W+3 loads per 4 outputs).
template<int W>
__device__ __forceinline__ void colslide(const float* __restrict__ base,
                                         float4 out[4]) {
    if constexpr (W == 1) {
        #pragma unroll
        for (int j = 0; j < 4; j++) out[j] = ld4s(base + j * RSTR);
    } else if constexpr (W <= 3) {
        float4 a[W + 3];
        #pragma unroll
        for (int k = 0; k < W + 3; k++) a[k] = ld4s(base + k * RSTR);
        #pragma unroll
        for (int j = 0; j < 4; j++) {
            float4 m = a[j];
            #pragma unroll
            for (int u = 1; u < W; u++) m = fmax4(m, a[j + u]);
            out[j] = m;
        }
    } else {
        float4 a0 = ld4s(base), a1 = ld4s(base + RSTR), a2 = ld4s(base + 2 * RSTR);
        float4 core = ld4s(base + 3 * RSTR);
        #pragma unroll
        for (int k = 4; k < W; k++) core = fmax4(core, ld4s(base + k * RSTR));
        float4 aW  = ld4s(base + W * RSTR);
        float4 aW1 = ld4s(base + (W + 1) * RSTR);
        float4 aW2 = ld4s(base + (W + 2) * RSTR);
        out[0] = fmax4(fmax4(core, a0), fmax4(a1, a2));
        out[1] = fmax4(fmax4(core, a1), fmax4(a2, aW));
        out[2] = fmax4(fmax4(core, a2), fmax4(aW, aW1));
        out[3] = fmax4(fmax4(core, aW), fmax4(aW1, aW2));
    }
}

// ---------------------------------------------------------------------------
// Row pass, full plane: 64 rows x 8 strips = 512 items = EXACTLY 2 iterations
// of 256 threads (no predication, no duplicated work). Thread owns cols
// [8s, 8s+8) of one row; neighbor cols via lane+-1 shuffles.
// a[i] = value at local col i-6; strips 0/7 mask halo to -inf (SAME padding).
// ---------------------------------------------------------------------------
template<int R>
__device__ __forceinline__ void row_pass(const float* __restrict__ xg,
                                         float* __restrict__ rowS,
                                         float* __restrict__ rowB) {
    const int t = threadIdx.x;
    const unsigned FULL = 0xffffffffu;

    #pragma unroll
    for (int k = 0; k < 2; k++) {
        const int idx = t + (k << 8);
        const int s   = idx & 7;
        const int row = idx >> 3;

        float a[20];
        {
            const float* rp = xg + row * HW + (s << 3);
            *reinterpret_cast<float4*>(&a[6])  = *reinterpret_cast<const float4*>(rp);
            *reinterpret_cast<float4*>(&a[10]) = *reinterpret_cast<const float4*>(rp + 4);
        }
        a[0] = __shfl_up_sync(FULL, a[8],  1);
        a[1] = __shfl_up_sync(FULL, a[9],  1);
        a[2] = __shfl_up_sync(FULL, a[10], 1);
        a[3] = __shfl_up_sync(FULL, a[11], 1);
        a[4] = __shfl_up_sync(FULL, a[12], 1);
        a[5] = __shfl_up_sync(FULL, a[13], 1);
        a[14] = __shfl_down_sync(FULL, a[6],  1);
        a[15] = __shfl_down_sync(FULL, a[7],  1);
        a[16] = __shfl_down_sync(FULL, a[8],  1);
        a[17] = __shfl_down_sync(FULL, a[9],  1);
        a[18] = __shfl_down_sync(FULL, a[10], 1);
        a[19] = __shfl_down_sync(FULL, a[11], 1);
        if (s == 0) { a[0] = a[1] = a[2] = a[3] = a[4] = a[5] = NEG_INF; }
        if (s == 7) { a[14] = a[15] = a[16] = a[17] = a[18] = a[19] = NEG_INF; }

        float mS[8], mB[8];
        if constexpr (R == 0) {
            #pragma unroll
            for (int j = 0; j < 8; j++) mS[j] = a[6 + j];
        } else if constexpr (R == 1) {
            #pragma unroll
            for (int j = 0; j < 8; j++)
                mS[j] = fmaxf(a[5 + j], fmaxf(a[6 + j], a[7 + j]));
        } else {
            float coreA = a[9 - R];
            #pragma unroll
            for (int u = 10 - R; u <= 6 + R; u++) coreA = fmaxf(coreA, a[u]);
            mS[0] = fmaxf(fmaxf(coreA, a[6 - R]), fmaxf(a[7 - R], a[8 - R]));
            mS[1] = fmaxf(fmaxf(coreA, a[7 - R]), fmaxf(a[8 - R], a[7 + R]));
            mS[2] = fmaxf(fmaxf(coreA, a[8 - R]), fmaxf(a[7 + R], a[8 + R]));
            mS[3] = fmaxf(fmaxf(coreA, a[7 + R]), fmaxf(a[8 + R], a[9 + R]));
            float coreB = a[13 - R];
            #pragma unroll
            for (int u = 14 - R; u <= 10 + R; u++) coreB = fmaxf(coreB, a[u]);
            mS[4] = fmaxf(fmaxf(coreB, a[10 - R]), fmaxf(a[11 - R], a[12 - R]));
            mS[5] = fmaxf(fmaxf(coreB, a[11 - R]), fmaxf(a[12 - R], a[11 + R]));
            mS[6] = fmaxf(fmaxf(coreB, a[12 - R]), fmaxf(a[11 + R], a[12 + R]));
            mS[7] = fmaxf(fmaxf(coreB, a[11 + R]), fmaxf(a[12 + R], a[13 + R]));
        }
        #pragma unroll
        for (int j = 0; j < 8; j++)
            mB[j] = fmaxf(mS[j], fmaxf(a[5 + j - R], a[7 + j + R]));

        const int ro = (row + 6) * RSTR + (s << 3);
        *reinterpret_cast<float4*>(rowS + ro)     = make_float4(mS[0], mS[1], mS[2], mS[3]);
        *reinterpret_cast<float4*>(rowS + ro + 4) = make_float4(mS[4], mS[5], mS[6], mS[7]);
        *reinterpret_cast<float4*>(rowB + ro)     = make_float4(mB[0], mB[1], mB[2], mB[3]);
        *reinterpret_cast<float4*>(rowB + ro + 4) = make_float4(mB[4], mB[5], mB[6], mB[7]);
    }
}

// ---------------------------------------------------------------------------
// Column pass (after barrier): 256 threads, thread owns 4 rows x 4 cols.
// Row y -> srow y+6; mS window [y-R+6, y+R+6] ⊂ [1,74], mB ⊂ [0,75].
// ---------------------------------------------------------------------------
template<int R>
__device__ __forceinline__ void col_pass(const float* __restrict__ xg,
                                         float* __restrict__ outg,
                                         const float* __restrict__ rowS,
                                         const float* __restrict__ rowB,
                                         float fb) {
    const int t = threadIdx.x;
    const int c4 = (t & 15) << 2;
    const int yl = (t >> 4) << 2;              // 0,4,...,60
    const float fs = 1.0f - fb;

    float4 part[4];
    {
        float4 mS4[4];
        colslide<2 * R + 1>(rowS + (yl - R + 6) * RSTR + c4, mS4);
        #pragma unroll
        for (int j = 0; j < 4; j++) {
            const float4 res = *reinterpret_cast<const float4*>(
                xg + (yl + j) * HW + c4);
            part[j].x = fmaf(fs, mS4[j].x, res.x);
            part[j].y = fmaf(fs, mS4[j].y, res.y);
            part[j].z = fmaf(fs, mS4[j].z, res.z);
            part[j].w = fmaf(fs, mS4[j].w, res.w);
        }
    }
    {
        float4 mB4[4];
        colslide<2 * R + 3>(rowB + (yl - R - 1 + 6) * RSTR + c4, mB4);
        #pragma unroll
        for (int j = 0; j < 4; j++) {
            float4 o;
            o.x = fmaf(fb, mB4[j].x, part[j].x);
            o.y = fmaf(fb, mB4[j].y, part[j].y);
            o.z = fmaf(fb, mB4[j].z, part[j].z);
            o.w = fmaf(fb, mB4[j].w, part[j].w);
            *reinterpret_cast<float4*>(outg + (yl + j) * HW + c4) = o;
        }
    }
}

// ---------------------------------------------------------------------------
// Kernel 3: one CTA (256 threads) per FULL plane, grid 4096, one barrier,
// zero halo redundancy, zero row-pass predication. 38 KB smem -> 4 CTAs/SM.
// ---------------------------------------------------------------------------
__global__ __launch_bounds__(256, 4) void pool_kernel(const float* __restrict__ x,
                                                      float* __restrict__ out) {
    __shared__ float rowS[NSROW * RSTR];
    __shared__ float rowB[NSROW * RSTR];

    const int t = threadIdx.x;
    const int plane = blockIdx.x;

    const float* xg = x + (size_t)plane * PLANE_ELEMS;
    float* outg = out + (size_t)plane * PLANE_ELEMS;
    const float2 route = g_route[plane];   // one LDG.64
    const int   r  = (int)route.x;
    const float fb = route.y;

    // fill pad srows 0..5 and 70..75 of both arrays with -inf (768 items)
    #pragma unroll
    for (int i = t; i < 12 * 64; i += 256) {
        const int pr = i >> 6, cc = i & 63;
        const int srow = (pr < 6) ? pr : (64 + pr);   // 0..5 or 70..75
        rowS[srow * RSTR + cc] = NEG_INF;
        rowB[srow * RSTR + cc] = NEG_INF;
    }

    switch (r) {
        case 0: row_pass<0>(xg, rowS, rowB); __syncthreads();
                col_pass<0>(xg, outg, rowS, rowB, fb); break;
        case 1: row_pass<1>(xg, rowS, rowB); __syncthreads();
                col_pass<1>(xg, outg, rowS, rowB, fb); break;
        case 2: row_pass<2>(xg, rowS, rowB); __syncthreads();
                col_pass<2>(xg, outg, rowS, rowB, fb); break;
        case 3: row_pass<3>(xg, rowS, rowB); __syncthreads();
                col_pass<3>(xg, outg, rowS, rowB, fb); break;
        case 4: row_pass<4>(xg, rowS, rowB); __syncthreads();
                col_pass<4>(xg, outg, rowS, rowB, fb); break;
        default: row_pass<5>(xg, rowS, rowB); __syncthreads();
                col_pass<5>(xg, outg, rowS, rowB, fb); break;
    }
}

// ---------------------------------------------------------------------------
extern "C" void kernel_launch(void* const* d_in, const int* in_sizes, int n_in,
                              void* d_out, int out_size) {
    const float* x  = (const float*)d_in[0];
    const float* w1 = (const float*)d_in[1];
    const float* b1 = (const float*)d_in[2];
    const float* w2 = (const float*)d_in[3];
    const float* b2 = (const float*)d_in[4];
    float* out = (float*)d_out;

    gap_kernel<<<NPLANES / 2, 256>>>(x);
    se_kernel<<<8, 512>>>(w1, b1, w2, b2);
    pool_kernel<<<NPLANES, 256>>>(x, out);
}

// round 16
// speedup vs baseline: 1.7234x; 1.5934x over previous
#include <cuda_runtime.h>
#include <math.h>
#include <float.h>

// Shapes (fixed): x [8,512,64,64] f32; w1 [32,512]; b1 [32]; w2 [512,32]; b2 [512]
#define NPLANES 4096
#define PLANE_ELEMS 4096
#define HW 64
#define NEG_INF (-FLT_MAX)

// Per-CTA smem: rowS/rowB for a FULL plane: 76 srows (64 real rows at srow
// 6..69, 6 -inf pad rows each side), stride 64.
#define RSTR 64
#define NSROW 76

// Scratch (no allocations allowed -> device globals)
__device__ float  g_gap[NPLANES];
__device__ float2 g_route[NPLANES];   // .x = (float)q, .y = frac_b

// ---------------------------------------------------------------------------
// Kernel 1: per-plane mean (two planes per block; at its read ceiling)
// ---------------------------------------------------------------------------
__global__ __launch_bounds__(256) void gap_kernel(const float* __restrict__ x) {
    const int p0 = blockIdx.x << 1;
    const float4* __restrict__ pa =
        reinterpret_cast<const float4*>(x + (size_t)p0 * PLANE_ELEMS);
    const float4* __restrict__ pb = pa + (PLANE_ELEMS / 4);

    float sa = 0.f, sb = 0.f;
    #pragma unroll
    for (int k = 0; k < 4; k++) {
        const int i = threadIdx.x + (k << 8);
        const float4 a = pa[i];
        const float4 b = pb[i];
        sa += (a.x + a.y) + (a.z + a.w);
        sb += (b.x + b.y) + (b.z + b.w);
    }
    #pragma unroll
    for (int off = 16; off > 0; off >>= 1) {
        sa += __shfl_down_sync(0xffffffffu, sa, off);
        sb += __shfl_down_sync(0xffffffffu, sb, off);
    }
    __shared__ float wsum[2][8];
    const int lane = threadIdx.x & 31, wid = threadIdx.x >> 5;
    if (lane == 0) { wsum[0][wid] = sa; wsum[1][wid] = sb; }
    __syncthreads();
    if (threadIdx.x < 2) {
        float t = 0.f;
        #pragma unroll
        for (int i = 0; i < 8; i++) t += wsum[threadIdx.x][i];
        g_gap[p0 + threadIdx.x] = t * (1.0f / (float)PLANE_ELEMS);
    }
}

// ---------------------------------------------------------------------------
// Kernel 2: SE bottleneck + routing. Fully parallel phase 1:
//   thread (e = t>>4, part = t&15) accumulates 8 float4 chunks of w1[e,:]*gap,
//   width-16 shuffle reduce -> hmid[e]. Phase 2 vectorized (8x LDG.128).
// ---------------------------------------------------------------------------
__global__ __launch_bounds__(512) void se_kernel(const float* __restrict__ w1,
                                                 const float* __restrict__ b1,
                                                 const float* __restrict__ w2,
                                                 const float* __restrict__ b2) {
    __shared__ float sgap[512];
    __shared__ float shmid[32];
    const int b = blockIdx.x;
    const int t = threadIdx.x;

    sgap[t] = g_gap[b * 512 + t];
    __syncthreads();

    // phase 1: hmid = relu(gap @ w1^T + b1), 16 threads per output
    {
        const int e = t >> 4, part = t & 15;
        const float4* __restrict__ wrow =
            reinterpret_cast<const float4*>(w1 + e * 512);
        const float4* __restrict__ gv =
            reinterpret_cast<const float4*>(sgap);
        float acc = 0.f;
        #pragma unroll
        for (int i = 0; i < 8; i++) {
            const int c4 = part + (i << 4);       // float4 index 0..127
            const float4 w = wrow[c4];
            const float4 g = gv[c4];
            acc += w.x * g.x + w.y * g.y + w.z * g.z + w.w * g.w;
        }
        #pragma unroll
        for (int off = 8; off > 0; off >>= 1)
            acc += __shfl_down_sync(0xffffffffu, acc, off, 16);
        if (part == 0) shmid[e] = fmaxf(acc + b1[e], 0.f);
    }
    __syncthreads();

    // phase 2: s = relu(hmid @ w2^T + b2); route
    float acc = b2[t];
    const float4* __restrict__ wr =
        reinterpret_cast<const float4*>(w2 + t * 32);
    #pragma unroll
    for (int j = 0; j < 8; j++) {
        const float4 w = wr[j];
        acc = fmaf(w.x, shmid[4 * j + 0],
              fmaf(w.y, shmid[4 * j + 1],
              fmaf(w.z, shmid[4 * j + 2],
              fmaf(w.w, shmid[4 * j + 3], acc))));
    }
    const float s = fmaxf(acc, 0.f);

    int q = (int)floorf(s);
    q = min(max(q, 0), 5);
    g_route[b * 512 + t] = make_float2((float)q, s - (float)q);
}

// ---------------------------------------------------------------------------
__device__ __forceinline__ float4 fmax4(float4 a, float4 b) {
    return make_float4(fmaxf(a.x, b.x), fmaxf(a.y, b.y),
                       fmaxf(a.z, b.z), fmaxf(a.w, b.w));
}
__device__ __forceinline__ float4 ld4s(const float* p) {
    return *reinterpret_cast<const float4*>(p);
}

// 4 sliding maxes of window W over float4 rows in smem at stride RSTR
// (shared-core streaming: W+3 loads per 4 outputs).
template<int W>
__device__ __forceinline__ void colslide(const float* __restrict__ base,
                                         float4 out[4]) {
    if constexpr (W == 1) {
        #pragma unroll
        for (int j = 0; j < 4; j++) out[j] = ld4s(base + j * RSTR);
    } else if constexpr (W <= 3) {
        float4 a[W + 3];
        #pragma unroll
        for (int k = 0; k < W + 3; k++) a[k] = ld4s(base + k * RSTR);
        #pragma unroll
        for (int j = 0; j < 4; j++) {
            float4 m = a[j];
            #pragma unroll
            for (int u = 1; u < W; u++) m = fmax4(m, a[j + u]);
            out[j] = m;
        }
    } else {
        float4 a0 = ld4s(base), a1 = ld4s(base + RSTR), a2 = ld4s(base + 2 * RSTR);
        float4 core = ld4s(base + 3 * RSTR);
        #pragma unroll
        for (int k = 4; k < W; k++) core = fmax4(core, ld4s(base + k * RSTR));
        float4 aW  = ld4s(base + W * RSTR);
        float4 aW1 = ld4s(base + (W + 1) * RSTR);
        float4 aW2 = ld4s(base + (W + 2) * RSTR);
        out[0] = fmax4(fmax4(core, a0), fmax4(a1, a2));
        out[1] = fmax4(fmax4(core, a1), fmax4(a2, aW));
        out[2] = fmax4(fmax4(core, a2), fmax4(aW, aW1));
        out[3] = fmax4(fmax4(core, aW), fmax4(aW1, aW2));
    }
}

// ---------------------------------------------------------------------------
// Row pass, full plane: 64 rows x 8 strips = 512 items = EXACTLY 2 iterations
// of 256 threads. Thread owns cols [8s, 8s+8) of one row; neighbors via
// lane+-1 shuffles. a[i] = local col i-6; strips 0/7 mask halo (SAME pad).
// ---------------------------------------------------------------------------
template<int R>
__device__ __forceinline__ void row_pass(const float* __restrict__ xg,
                                         float* __restrict__ rowS,
                                         float* __restrict__ rowB) {
    const int t = threadIdx.x;
    const unsigned FULL = 0xffffffffu;

    #pragma unroll
    for (int k = 0; k < 2; k++) {
        const int idx = t + (k << 8);
        const int s   = idx & 7;
        const int row = idx >> 3;

        float a[20];
        {
            const float* rp = xg + row * HW + (s << 3);
            *reinterpret_cast<float4*>(&a[6])  = *reinterpret_cast<const float4*>(rp);
            *reinterpret_cast<float4*>(&a[10]) = *reinterpret_cast<const float4*>(rp + 4);
        }
        a[0] = __shfl_up_sync(FULL, a[8],  1);
        a[1] = __shfl_up_sync(FULL, a[9],  1);
        a[2] = __shfl_up_sync(FULL, a[10], 1);
        a[3] = __shfl_up_sync(FULL, a[11], 1);
        a[4] = __shfl_up_sync(FULL, a[12], 1);
        a[5] = __shfl_up_sync(FULL, a[13], 1);
        a[14] = __shfl_down_sync(FULL, a[6],  1);
        a[15] = __shfl_down_sync(FULL, a[7],  1);
        a[16] = __shfl_down_sync(FULL, a[8],  1);
        a[17] = __shfl_down_sync(FULL, a[9],  1);
        a[18] = __shfl_down_sync(FULL, a[10], 1);
        a[19] = __shfl_down_sync(FULL, a[11], 1);
        if (s == 0) { a[0] = a[1] = a[2] = a[3] = a[4] = a[5] = NEG_INF; }
        if (s == 7) { a[14] = a[15] = a[16] = a[17] = a[18] = a[19] = NEG_INF; }

        float mS[8], mB[8];
        if constexpr (R == 0) {
            #pragma unroll
            for (int j = 0; j < 8; j++) mS[j] = a[6 + j];
        } else if constexpr (R == 1) {
            #pragma unroll
            for (int j = 0; j < 8; j++)
                mS[j] = fmaxf(a[5 + j], fmaxf(a[6 + j], a[7 + j]));
        } else {
            float coreA = a[9 - R];
            #pragma unroll
            for (int u = 10 - R; u <= 6 + R; u++) coreA = fmaxf(coreA, a[u]);
            mS[0] = fmaxf(fmaxf(coreA, a[6 - R]), fmaxf(a[7 - R], a[8 - R]));
            mS[1] = fmaxf(fmaxf(coreA, a[7 - R]), fmaxf(a[8 - R], a[7 + R]));
            mS[2] = fmaxf(fmaxf(coreA, a[8 - R]), fmaxf(a[7 + R], a[8 + R]));
            mS[3] = fmaxf(fmaxf(coreA, a[7 + R]), fmaxf(a[8 + R], a[9 + R]));
            float coreB = a[13 - R];
            #pragma unroll
            for (int u = 14 - R; u <= 10 + R; u++) coreB = fmaxf(coreB, a[u]);
            mS[4] = fmaxf(fmaxf(coreB, a[10 - R]), fmaxf(a[11 - R], a[12 - R]));
            mS[5] = fmaxf(fmaxf(coreB, a[11 - R]), fmaxf(a[12 - R], a[11 + R]));
            mS[6] = fmaxf(fmaxf(coreB, a[12 - R]), fmaxf(a[11 + R], a[12 + R]));
            mS[7] = fmaxf(fmaxf(coreB, a[11 + R]), fmaxf(a[12 + R], a[13 + R]));
        }
        #pragma unroll
        for (int j = 0; j < 8; j++)
            mB[j] = fmaxf(mS[j], fmaxf(a[5 + j - R], a[7 + j + R]));

        const int ro = (row + 6) * RSTR + (s << 3);
        *reinterpret_cast<float4*>(rowS + ro)     = make_float4(mS[0], mS[1], mS[2], mS[3]);
        *reinterpret_cast<float4*>(rowS + ro + 4) = make_float4(mS[4], mS[5], mS[6], mS[7]);
        *reinterpret_cast<float4*>(rowB + ro)     = make_float4(mB[0], mB[1], mB[2], mB[3]);
        *reinterpret_cast<float4*>(rowB + ro + 4) = make_float4(mB[4], mB[5], mB[6], mB[7]);
    }
}

// ---------------------------------------------------------------------------
// Column pass (after barrier): 256 threads, thread owns 4 rows x 4 cols.
// Row y -> srow y+6; mS window [y-R+6, y+R+6] ⊂ [1,74], mB ⊂ [0,75].
// ---------------------------------------------------------------------------
template<int R>
__device__ __forceinline__ void col_pass(const float* __restrict__ xg,
                                         float* __restrict__ outg,
                                         const float* __restrict__ rowS,
                                         const float* __restrict__ rowB,
                                         float fb) {
    const int t = threadIdx.x;
    const int c4 = (t & 15) << 2;
    const int yl = (t >> 4) << 2;              // 0,4,...,60
    const float fs = 1.0f - fb;

    float4 part[4];
    {
        float4 mS4[4];
        colslide<2 * R + 1>(rowS + (yl - R + 6) * RSTR + c4, mS4);
        #pragma unroll
        for (int j = 0; j < 4; j++) {
            const float4 res = *reinterpret_cast<const float4*>(
                xg + (yl + j) * HW + c4);
            part[j].x = fmaf(fs, mS4[j].x, res.x);
            part[j].y = fmaf(fs, mS4[j].y, res.y);
            part[j].z = fmaf(fs, mS4[j].z, res.z);
            part[j].w = fmaf(fs, mS4[j].w, res.w);
        }
    }
    {
        float4 mB4[4];
        colslide<2 * R + 3>(rowB + (yl - R - 1 + 6) * RSTR + c4, mB4);
        #pragma unroll
        for (int j = 0; j < 4; j++) {
            float4 o;
            o.x = fmaf(fb, mB4[j].x, part[j].x);
            o.y = fmaf(fb, mB4[j].y, part[j].y);
            o.z = fmaf(fb, mB4[j].z, part[j].z);
            o.w = fmaf(fb, mB4[j].w, part[j].w);
            *reinterpret_cast<float4*>(outg + (yl + j) * HW + c4) = o;
        }
    }
}

// ---------------------------------------------------------------------------
// Kernel 3: one CTA (256 threads) per FULL plane, grid 4096, one barrier,
// zero halo redundancy, zero row-pass predication. 38 KB smem -> 4 CTAs/SM.
// ---------------------------------------------------------------------------
__global__ __launch_bounds__(256, 4) void pool_kernel(const float* __restrict__ x,
                                                      float* __restrict__ out) {
    __shared__ float rowS[NSROW * RSTR];
    __shared__ float rowB[NSROW * RSTR];

    const int t = threadIdx.x;
    const int plane = blockIdx.x;

    const float* xg = x + (size_t)plane * PLANE_ELEMS;
    float* outg = out + (size_t)plane * PLANE_ELEMS;
    const float2 route = g_route[plane];   // one LDG.64
    const int   r  = (int)route.x;
    const float fb = route.y;

    // fill pad srows 0..5 and 70..75 of both arrays with -inf (768 items)
    #pragma unroll
    for (int i = t; i < 12 * 64; i += 256) {
        const int pr = i >> 6, cc = i & 63;
        const int srow = (pr < 6) ? pr : (64 + pr);   // 0..5 or 70..75
        rowS[srow * RSTR + cc] = NEG_INF;
        rowB[srow * RSTR + cc] = NEG_INF;
    }

    switch (r) {
        case 0: row_pass<0>(xg, rowS, rowB); __syncthreads();
                col_pass<0>(xg, outg, rowS, rowB, fb); break;
        case 1: row_pass<1>(xg, rowS, rowB); __syncthreads();
                col_pass<1>(xg, outg, rowS, rowB, fb); break;
        case 2: row_pass<2>(xg, rowS, rowB); __syncthreads();
                col_pass<2>(xg, outg, rowS, rowB, fb); break;
        case 3: row_pass<3>(xg, rowS, rowB); __syncthreads();
                col_pass<3>(xg, outg, rowS, rowB, fb); break;
        case 4: row_pass<4>(xg, rowS, rowB); __syncthreads();
                col_pass<4>(xg, outg, rowS, rowB, fb); break;
        default: row_pass<5>(xg, rowS, rowB); __syncthreads();
                col_pass<5>(xg, outg, rowS, rowB, fb); break;
    }
}

// ---------------------------------------------------------------------------
extern "C" void kernel_launch(void* const* d_in, const int* in_sizes, int n_in,
                              void* d_out, int out_size) {
    const float* x  = (const float*)d_in[0];
    const float* w1 = (const float*)d_in[1];
    const float* b1 = (const float*)d_in[2];
    const float* w2 = (const float*)d_in[3];
    const float* b2 = (const float*)d_in[4];
    float* out = (float*)d_out;

    gap_kernel<<<NPLANES / 2, 256>>>(x);
    se_kernel<<<8, 512>>>(w1, b1, w2, b2);
    pool_kernel<<<NPLANES, 256>>>(x, out);
}

// round 17
// speedup vs baseline: 1.8716x; 1.0860x over previous
#include <cuda_runtime.h>
#include <math.h>
#include <float.h>

// Shapes (fixed): x [8,512,64,64] f32; w1 [32,512]; b1 [32]; w2 [512,32]; b2 [512]
#define NPLANES 4096
#define PLANE_ELEMS 4096
#define HW 64
#define NEG_INF (-FLT_MAX)

// Per-CTA smem: ONE array (rowS) for a full plane: 76 srows (real rows at
// srow 6..69, 6 -inf pad rows each side), stride 64. 19456 B.
#define RSTR 64
#define NSROW 76

// Scratch (no allocations allowed -> device globals)
__device__ float  g_gap[NPLANES];
__device__ float2 g_route[NPLANES];   // .x = (float)q, .y = frac_b

// ---------------------------------------------------------------------------
// Kernel 1: per-plane mean (two planes per block; at its read ceiling)
// ---------------------------------------------------------------------------
__global__ __launch_bounds__(256) void gap_kernel(const float* __restrict__ x) {
    const int p0 = blockIdx.x << 1;
    const float4* __restrict__ pa =
        reinterpret_cast<const float4*>(x + (size_t)p0 * PLANE_ELEMS);
    const float4* __restrict__ pb = pa + (PLANE_ELEMS / 4);

    float sa = 0.f, sb = 0.f;
    #pragma unroll
    for (int k = 0; k < 4; k++) {
        const int i = threadIdx.x + (k << 8);
        const float4 a = pa[i];
        const float4 b = pb[i];
        sa += (a.x + a.y) + (a.z + a.w);
        sb += (b.x + b.y) + (b.z + b.w);
    }
    #pragma unroll
    for (int off = 16; off > 0; off >>= 1) {
        sa += __shfl_down_sync(0xffffffffu, sa, off);
        sb += __shfl_down_sync(0xffffffffu, sb, off);
    }
    __shared__ float wsum[2][8];
    const int lane = threadIdx.x & 31, wid = threadIdx.x >> 5;
    if (lane == 0) { wsum[0][wid] = sa; wsum[1][wid] = sb; }
    __syncthreads();
    if (threadIdx.x < 2) {
        float t = 0.f;
        #pragma unroll
        for (int i = 0; i < 8; i++) t += wsum[threadIdx.x][i];
        g_gap[p0 + threadIdx.x] = t * (1.0f / (float)PLANE_ELEMS);
    }
}

// ---------------------------------------------------------------------------
// Kernel 2: SE bottleneck + routing (parallel phase 1, vectorized phase 2)
// ---------------------------------------------------------------------------
__global__ __launch_bounds__(512) void se_kernel(const float* __restrict__ w1,
                                                 const float* __restrict__ b1,
                                                 const float* __restrict__ w2,
                                                 const float* __restrict__ b2) {
    __shared__ float sgap[512];
    __shared__ float shmid[32];
    const int b = blockIdx.x;
    const int t = threadIdx.x;

    sgap[t] = g_gap[b * 512 + t];
    __syncthreads();

    // phase 1: hmid = relu(gap @ w1^T + b1), 16 threads per output
    {
        const int e = t >> 4, part = t & 15;
        const float4* __restrict__ wrow =
            reinterpret_cast<const float4*>(w1 + e * 512);
        const float4* __restrict__ gv =
            reinterpret_cast<const float4*>(sgap);
        float acc = 0.f;
        #pragma unroll
        for (int i = 0; i < 8; i++) {
            const int c4 = part + (i << 4);
            const float4 w = wrow[c4];
            const float4 g = gv[c4];
            acc += w.x * g.x + w.y * g.y + w.z * g.z + w.w * g.w;
        }
        #pragma unroll
        for (int off = 8; off > 0; off >>= 1)
            acc += __shfl_down_sync(0xffffffffu, acc, off, 16);
        if (part == 0) shmid[e] = fmaxf(acc + b1[e], 0.f);
    }
    __syncthreads();

    // phase 2: s = relu(hmid @ w2^T + b2); route
    float acc = b2[t];
    const float4* __restrict__ wr =
        reinterpret_cast<const float4*>(w2 + t * 32);
    #pragma unroll
    for (int j = 0; j < 8; j++) {
        const float4 w = wr[j];
        acc = fmaf(w.x, shmid[4 * j + 0],
              fmaf(w.y, shmid[4 * j + 1],
              fmaf(w.z, shmid[4 * j + 2],
              fmaf(w.w, shmid[4 * j + 3], acc))));
    }
    const float s = fmaxf(acc, 0.f);

    int q = (int)floorf(s);
    q = min(max(q, 0), 5);
    g_route[b * 512 + t] = make_float2((float)q, s - (float)q);
}

// ---------------------------------------------------------------------------
__device__ __forceinline__ float4 fmax4(float4 a, float4 b) {
    return make_float4(fmaxf(a.x, b.x), fmaxf(a.y, b.y),
                       fmaxf(a.z, b.z), fmaxf(a.w, b.w));
}
__device__ __forceinline__ float4 ld4s(const float* p) {
    return *reinterpret_cast<const float4*>(p);
}

// ---------------------------------------------------------------------------
// Row pass, full plane, S only: 64 rows x 8 strips = 512 items = EXACTLY 2
// iterations of 256 threads. Thread owns cols [8s, 8s+8) of one row.
// a[i] = local col i-6; strips 0/7 mask halo (SAME padding).
// ---------------------------------------------------------------------------
template<int R>
__device__ __forceinline__ void row_pass(const float* __restrict__ xg,
                                         float* __restrict__ rowS) {
    const int t = threadIdx.x;
    const unsigned FULL = 0xffffffffu;

    #pragma unroll
    for (int k = 0; k < 2; k++) {
        const int idx = t + (k << 8);
        const int s   = idx & 7;
        const int row = idx >> 3;

        float a[20];
        {
            const float* rp = xg + row * HW + (s << 3);
            *reinterpret_cast<float4*>(&a[6])  = *reinterpret_cast<const float4*>(rp);
            *reinterpret_cast<float4*>(&a[10]) = *reinterpret_cast<const float4*>(rp + 4);
        }
        a[1]  = __shfl_up_sync(FULL, a[9],  1);
        a[2]  = __shfl_up_sync(FULL, a[10], 1);
        a[3]  = __shfl_up_sync(FULL, a[11], 1);
        a[4]  = __shfl_up_sync(FULL, a[12], 1);
        a[5]  = __shfl_up_sync(FULL, a[13], 1);
        a[14] = __shfl_down_sync(FULL, a[6],  1);
        a[15] = __shfl_down_sync(FULL, a[7],  1);
        a[16] = __shfl_down_sync(FULL, a[8],  1);
        a[17] = __shfl_down_sync(FULL, a[9],  1);
        a[18] = __shfl_down_sync(FULL, a[10], 1);
        if (s == 0) { a[1] = a[2] = a[3] = a[4] = a[5] = NEG_INF; }
        if (s == 7) { a[14] = a[15] = a[16] = a[17] = a[18] = NEG_INF; }

        float mS[8];
        if constexpr (R == 0) {
            #pragma unroll
            for (int j = 0; j < 8; j++) mS[j] = a[6 + j];
        } else if constexpr (R == 1) {
            #pragma unroll
            for (int j = 0; j < 8; j++)
                mS[j] = fmaxf(a[5 + j], fmaxf(a[6 + j], a[7 + j]));
        } else {
            float coreA = a[9 - R];
            #pragma unroll
            for (int u = 10 - R; u <= 6 + R; u++) coreA = fmaxf(coreA, a[u]);
            mS[0] = fmaxf(fmaxf(coreA, a[6 - R]), fmaxf(a[7 - R], a[8 - R]));
            mS[1] = fmaxf(fmaxf(coreA, a[7 - R]), fmaxf(a[8 - R], a[7 + R]));
            mS[2] = fmaxf(fmaxf(coreA, a[8 - R]), fmaxf(a[7 + R], a[8 + R]));
            mS[3] = fmaxf(fmaxf(coreA, a[7 + R]), fmaxf(a[8 + R], a[9 + R]));
            float coreB = a[13 - R];
            #pragma unroll
            for (int u = 14 - R; u <= 10 + R; u++) coreB = fmaxf(coreB, a[u]);
            mS[4] = fmaxf(fmaxf(coreB, a[10 - R]), fmaxf(a[11 - R], a[12 - R]));
            mS[5] = fmaxf(fmaxf(coreB, a[11 - R]), fmaxf(a[12 - R], a[11 + R]));
            mS[6] = fmaxf(fmaxf(coreB, a[12 - R]), fmaxf(a[11 + R], a[12 + R]));
            mS[7] = fmaxf(fmaxf(coreB, a[11 + R]), fmaxf(a[12 + R], a[13 + R]));
        }

        const int ro = (row + 6) * RSTR + (s << 3);
        *reinterpret_cast<float4*>(rowS + ro)     = make_float4(mS[0], mS[1], mS[2], mS[3]);
        *reinterpret_cast<float4*>(rowS + ro + 4) = make_float4(mS[4], mS[5], mS[6], mS[7]);
    }
}

// ---------------------------------------------------------------------------
// Column-pass group: 2 output rows (y0, y0+1) x 4 cols from rowS ONLY.
//   mS_j   = vert max radius R   of rowS  (exact poolS after row pass)
//   mBc_j  = vert max radius R+1 of rowS
//   poolB_j= horiz max radius 1 of mBc (via lane shuffles)   [rowB identity]
// ---------------------------------------------------------------------------
template<int R>
__device__ __forceinline__ void col_group2(const float* __restrict__ rowS,
                                           const float* __restrict__ xg,
                                           float* __restrict__ outg,
                                           int y0, int c, int c4,
                                           float fb, float fs) {
    const unsigned FULL = 0xffffffffu;
    const float* bp = rowS + (y0 + 6) * RSTR + c4;   // row y0 base

    float4 mS0, mS1, mBc0, mBc1;
    if constexpr (R == 0) {
        const float4 rm1 = ld4s(bp - RSTR);
        const float4 r0  = ld4s(bp);
        const float4 r1  = ld4s(bp + RSTR);
        const float4 r2  = ld4s(bp + 2 * RSTR);
        mS0 = r0; mS1 = r1;
        mBc0 = fmax4(rm1, fmax4(r0, r1));
        mBc1 = fmax4(r0,  fmax4(r1, r2));
    } else {
        // core = max rows [y0+1-R, y0+R]  (2R rows)
        float4 core = ld4s(bp + (1 - R) * RSTR);
        #pragma unroll
        for (int k = 1; k < 2 * R; k++)
            core = fmax4(core, ld4s(bp + (1 - R + k) * RSTR));
        const float4 rA = ld4s(bp + (-R - 1) * RSTR);
        const float4 rB = ld4s(bp + (-R) * RSTR);
        const float4 rC = ld4s(bp + (R + 1) * RSTR);
        const float4 rD = ld4s(bp + (R + 2) * RSTR);
        mS0 = fmax4(core, rB);
        mS1 = fmax4(core, rC);
        mBc0 = fmax4(mS0, fmax4(rA, rC));
        mBc1 = fmax4(mS1, fmax4(rB, rD));
    }

    // partial = fs * poolS + residual
    float4 p0, p1;
    {
        const float4 res0 = ld4s(xg + y0 * HW + c4);
        const float4 res1 = ld4s(xg + (y0 + 1) * HW + c4);
        p0.x = fmaf(fs, mS0.x, res0.x); p0.y = fmaf(fs, mS0.y, res0.y);
        p0.z = fmaf(fs, mS0.z, res0.z); p0.w = fmaf(fs, mS0.w, res0.w);
        p1.x = fmaf(fs, mS1.x, res1.x); p1.y = fmaf(fs, mS1.y, res1.y);
        p1.z = fmaf(fs, mS1.z, res1.z); p1.w = fmaf(fs, mS1.w, res1.w);
    }

    // horizontal radius-1 max on mBc via neighbor-lane shuffles
    float L0 = __shfl_up_sync(FULL, mBc0.w, 1);
    float L1 = __shfl_up_sync(FULL, mBc1.w, 1);
    float R0 = __shfl_down_sync(FULL, mBc0.x, 1);
    float R1 = __shfl_down_sync(FULL, mBc1.x, 1);
    if (c == 0)  { L0 = NEG_INF; L1 = NEG_INF; }
    if (c == 15) { R0 = NEG_INF; R1 = NEG_INF; }

    float4 o0, o1;
    o0.x = fmaf(fb, fmaxf(L0,     fmaxf(mBc0.x, mBc0.y)), p0.x);
    o0.y = fmaf(fb, fmaxf(mBc0.x, fmaxf(mBc0.y, mBc0.z)), p0.y);
    o0.z = fmaf(fb, fmaxf(mBc0.y, fmaxf(mBc0.z, mBc0.w)), p0.z);
    o0.w = fmaf(fb, fmaxf(mBc0.z, fmaxf(mBc0.w, R0)),     p0.w);
    o1.x = fmaf(fb, fmaxf(L1,     fmaxf(mBc1.x, mBc1.y)), p1.x);
    o1.y = fmaf(fb, fmaxf(mBc1.x, fmaxf(mBc1.y, mBc1.z)), p1.y);
    o1.z = fmaf(fb, fmaxf(mBc1.y, fmaxf(mBc1.z, mBc1.w)), p1.z);
    o1.w = fmaf(fb, fmaxf(mBc1.z, fmaxf(mBc1.w, R1)),     p1.w);

    __stcs(reinterpret_cast<float4*>(outg + y0 * HW + c4), o0);       // evict-
    __stcs(reinterpret_cast<float4*>(outg + (y0 + 1) * HW + c4), o1); // first
}

template<int R>
__device__ __forceinline__ void col_pass(const float* __restrict__ xg,
                                         float* __restrict__ outg,
                                         const float* __restrict__ rowS,
                                         float fb) {
    const int t = threadIdx.x;
    const int c = t & 15;
    const int c4 = c << 2;
    const int yl = (t >> 4) << 2;              // 0,4,...,60
    const float fs = 1.0f - fb;
    col_group2<R>(rowS, xg, outg, yl,     c, c4, fb, fs);
    col_group2<R>(rowS, xg, outg, yl + 2, c, c4, fb, fs);
}

// ---------------------------------------------------------------------------
// Kernel 3: one CTA (256 threads) per full plane, grid 4096, one barrier.
// Single smem array (19.5 KB) -> 5 CTAs/SM (40 warps).
// ---------------------------------------------------------------------------
__global__ __launch_bounds__(256, 5) void pool_kernel(const float* __restrict__ x,
                                                      float* __restrict__ out) {
    __shared__ float rowS[NSROW * RSTR];

    const int t = threadIdx.x;
    const int plane = blockIdx.x;

    const float* xg = x + (size_t)plane * PLANE_ELEMS;
    float* outg = out + (size_t)plane * PLANE_ELEMS;
    const float2 route = g_route[plane];   // one LDG.64
    const int   r  = (int)route.x;
    const float fb = route.y;

    // fill pad srows 0..5 and 70..75 with -inf
    #pragma unroll
    for (int i = t; i < 12 * 64; i += 256) {
        const int pr = i >> 6, cc = i & 63;
        const int srow = (pr < 6) ? pr : (64 + pr);
        rowS[srow * RSTR + cc] = NEG_INF;
    }

    switch (r) {
        case 0: row_pass<0>(xg, rowS); __syncthreads();
                col_pass<0>(xg, outg, rowS, fb); break;
        case 1: row_pass<1>(xg, rowS); __syncthreads();
                col_pass<1>(xg, outg, rowS, fb); break;
        case 2: row_pass<2>(xg, rowS); __syncthreads();
                col_pass<2>(xg, outg, rowS, fb); break;
        case 3: row_pass<3>(xg, rowS); __syncthreads();
                col_pass<3>(xg, outg, rowS, fb); break;
        case 4: row_pass<4>(xg, rowS); __syncthreads();
                col_pass<4>(xg, outg, rowS, fb); break;
        default: row_pass<5>(xg, rowS); __syncthreads();
                col_pass<5>(xg, outg, rowS, fb); break;
    }
}

// ---------------------------------------------------------------------------
extern "C" void kernel_launch(void* const* d_in, const int* in_sizes, int n_in,
                              void* d_out, int out_size) {
    const float* x  = (const float*)d_in[0];
    const float* w1 = (const float*)d_in[1];
    const float* b1 = (const float*)d_in[2];
    const float* w2 = (const float*)d_in[3];
    const float* b2 = (const float*)d_in[4];
    float* out = (float*)d_out;

    gap_kernel<<<NPLANES / 2, 256>>>(x);
    se_kernel<<<8, 512>>>(w1, b1, w2, b2);
    pool_kernel<<<NPLANES, 256>>>(x, out);
}